// round 5
// baseline (speedup 1.0000x reference)
#include <cuda_runtime.h>

#define NN 100000
#define EE 1600000
#define ETOT (EE + NN)      // edges + self loops
#define FH 128              // heads*channels for layers 0/1
#define CC 32               // channels per head
#define NCLS 40
#define FULL 0xffffffffu

// ---------------- scratch (device globals; no allocation allowed) ------------
__device__ __align__(16) float g_h[NN * FH];      // transformed features (x @ W)
__device__ __align__(16) float g_feat[NN * FH];   // layer output features
__device__ __align__(16) float g_e[(size_t)ETOT * 4];   // per-edge per-head exp weights (CSR order)
__device__ __align__(16) float g_as[NN * 4];
__device__ __align__(16) float g_ad[NN * 4];
__device__ __align__(16) float g_den[NN * 4];
__device__ int   g_src[ETOT];
__device__ int   g_dst[ETOT];
__device__ int   g_csrc[ETOT];        // CSR: src per edge, grouped by dst
__device__ int   g_deg[NN];
__device__ int   g_rowptr[NN + 1];
__device__ int   g_cursor[NN];
__device__ int   g_bsum[128];
__device__ int   g_boff[128];
__device__ int   g_is64;

#define SCAN_CHUNK 1024
#define NB ((NN + SCAN_CHUNK - 1) / SCAN_CHUNK)   // 98

static inline int cdiv(int a, int b) { return (a + b - 1) / b; }

// ================= edge ingestion + CSR build =================================
__global__ void detect_dtype(const int* __restrict__ e) {
    if (blockIdx.x != 0 || threadIdx.x != 0) return;
    int any = 0;
    for (int i = 0; i < 4096; i++) any |= e[2 * i + 1];
    g_is64 = (any == 0) ? 1 : 0;
}

__global__ void clear_deg() {
    int i = blockIdx.x * blockDim.x + threadIdx.x;
    if (i < NN) g_deg[i] = 0;
}

__global__ void build_edges(const int* __restrict__ e) {
    int i = blockIdx.x * blockDim.x + threadIdx.x;
    if (i >= ETOT) return;
    int s, d;
    if (i < EE) {
        if (g_is64) { s = e[2 * (size_t)i]; d = e[2 * ((size_t)EE + i)]; }
        else        { s = e[i];             d = e[EE + i]; }
    } else {
        s = i - EE; d = i - EE;
    }
    g_src[i] = s;
    g_dst[i] = d;
    atomicAdd(&g_deg[d], 1);
}

__global__ void scan_a() {
    __shared__ int sm[256];
    int blk = blockIdx.x, tid = threadIdx.x;
    int base = blk * SCAN_CHUNK + tid * 4;
    int t = 0;
    #pragma unroll
    for (int i = 0; i < 4; i++) if (base + i < NN) t += g_deg[base + i];
    sm[tid] = t;
    __syncthreads();
    for (int o = 128; o > 0; o >>= 1) {
        if (tid < o) sm[tid] += sm[tid + o];
        __syncthreads();
    }
    if (tid == 0) g_bsum[blk] = sm[0];
}

__global__ void scan_b() {
    if (threadIdx.x != 0) return;
    int run = 0;
    for (int i = 0; i < NB; i++) { g_boff[i] = run; run += g_bsum[i]; }
}

__global__ void scan_c() {
    int blk = blockIdx.x, tid = threadIdx.x;
    int base = blk * SCAN_CHUNK + tid * 4;
    int v[4];
    #pragma unroll
    for (int i = 0; i < 4; i++) v[i] = (base + i < NN) ? g_deg[base + i] : 0;
    int tsum = v[0] + v[1] + v[2] + v[3];
    int lane = tid & 31, wid = tid >> 5;
    int inc = tsum;
    #pragma unroll
    for (int o = 1; o < 32; o <<= 1) {
        int t = __shfl_up_sync(FULL, inc, o);
        if (lane >= o) inc += t;
    }
    __shared__ int wsum[8];
    if (lane == 31) wsum[wid] = inc;
    __syncthreads();
    if (tid < 8) {
        int t = wsum[tid];
        #pragma unroll
        for (int o = 1; o < 8; o <<= 1) {
            int u = __shfl_up_sync(0xff, t, o);
            if (tid >= o) t += u;
        }
        wsum[tid] = t;
    }
    __syncthreads();
    int excl = inc - tsum + (wid > 0 ? wsum[wid - 1] : 0) + g_boff[blk];
    #pragma unroll
    for (int i = 0; i < 4; i++) {
        if (base + i < NN) { g_rowptr[base + i] = excl; g_cursor[base + i] = excl; }
        excl += v[i];
    }
    if (blk == 0 && tid == 0) g_rowptr[NN] = ETOT;
}

__global__ void scatter_csr() {
    int i = blockIdx.x * blockDim.x + threadIdx.x;
    if (i >= ETOT) return;
    int pos = atomicAdd(&g_cursor[g_dst[i]], 1);
    g_csrc[pos] = g_src[i];
}

// ================= GEMM (big): Y[N,128] = X[N,128] @ W[128,128] ================
// 128 threads, BM=64, BN=128, 8x8 per thread, k staged in chunks of 32.
__global__ void gemm_big(const float* __restrict__ X, const float* __restrict__ W,
                         float* __restrict__ Y) {
    __shared__ __align__(16) float sxT[32 * 68];   // [k][row]
    __shared__ __align__(16) float sw[32 * 132];   // [k][col]
    const int tid = threadIdx.x;
    const int r0 = blockIdx.x * 64;
    const int rg = (tid >> 4) * 8;     // 8 row groups
    const int cg = (tid & 15) * 8;     // 16 col groups

    float acc[8][8];
    #pragma unroll
    for (int i = 0; i < 8; i++)
        #pragma unroll
        for (int j = 0; j < 8; j++) acc[i][j] = 0.0f;

    for (int kk = 0; kk < 128; kk += 32) {
        // X tile: 64 rows x 32 k, loaded as float4, stored transposed
        #pragma unroll
        for (int it = 0; it < 4; it++) {
            int idx = tid + it * 128;          // [0,512)
            int row = idx >> 3;
            int kq  = idx & 7;
            int grow = r0 + row; if (grow >= NN) grow = NN - 1;
            float4 v = *(const float4*)&X[(size_t)grow * 128 + kk + kq * 4];
            sxT[(kq * 4 + 0) * 68 + row] = v.x;
            sxT[(kq * 4 + 1) * 68 + row] = v.y;
            sxT[(kq * 4 + 2) * 68 + row] = v.z;
            sxT[(kq * 4 + 3) * 68 + row] = v.w;
        }
        // W tile: 32 k x 128 cols, float4
        #pragma unroll
        for (int it = 0; it < 8; it++) {
            int idx = tid + it * 128;          // [0,1024)
            int k  = idx >> 5;
            int cq = idx & 31;
            *(float4*)&sw[k * 132 + cq * 4] =
                *(const float4*)&W[(size_t)(kk + k) * 128 + cq * 4];
        }
        __syncthreads();

        #pragma unroll
        for (int k = 0; k < 32; k++) {
            float4 a0 = *(const float4*)&sxT[k * 68 + rg];
            float4 a1 = *(const float4*)&sxT[k * 68 + rg + 4];
            float4 b0 = *(const float4*)&sw[k * 132 + cg];
            float4 b1 = *(const float4*)&sw[k * 132 + cg + 4];
            float ar[8] = {a0.x, a0.y, a0.z, a0.w, a1.x, a1.y, a1.z, a1.w};
            float bc[8] = {b0.x, b0.y, b0.z, b0.w, b1.x, b1.y, b1.z, b1.w};
            #pragma unroll
            for (int i = 0; i < 8; i++)
                #pragma unroll
                for (int j = 0; j < 8; j++)
                    acc[i][j] += ar[i] * bc[j];
        }
        __syncthreads();
    }

    #pragma unroll
    for (int i = 0; i < 8; i++) {
        int row = r0 + rg + i;
        if (row < NN) {
            float4 o0 = {acc[i][0], acc[i][1], acc[i][2], acc[i][3]};
            float4 o1 = {acc[i][4], acc[i][5], acc[i][6], acc[i][7]};
            *(float4*)&Y[(size_t)row * 128 + cg]     = o0;
            *(float4*)&Y[(size_t)row * 128 + cg + 4] = o1;
        }
    }
}

// ================= GEMM (small): Y[N,32] = X[N,128] @ W[128,32] ================
template<int BN, int TN>
__global__ void gemm64(const float* __restrict__ X, const float* __restrict__ W,
                       float* __restrict__ Y, int Kout) {
    constexpr int SXP = 68;
    constexpr int SWP = BN + 4;
    __shared__ __align__(16) float sxT[64 * SXP];
    __shared__ __align__(16) float sw[64 * SWP];
    const int tid = threadIdx.x;
    const int r0 = blockIdx.x * 64;
    const int j0 = blockIdx.y * BN;

    const int rg = (tid >> 4) * 4;
    const int cg = (tid & 15) * TN;
    float acc[4][TN];
    #pragma unroll
    for (int i = 0; i < 4; i++)
        #pragma unroll
        for (int j = 0; j < TN; j++) acc[i][j] = 0.0f;

    for (int kk = 0; kk < 128; kk += 64) {
        for (int idx = tid; idx < 64 * 64; idx += 256) {
            int k = idx & 63;
            int r = idx >> 6;
            int row = r0 + r; if (row >= NN) row = NN - 1;
            sxT[k * SXP + r] = X[(size_t)row * 128 + kk + k];
        }
        for (int idx = tid; idx < 64 * BN / 4; idx += 256) {
            int k = idx / (BN / 4);
            int jq = (idx % (BN / 4)) * 4;
            *(float4*)&sw[k * SWP + jq] =
                *(const float4*)&W[(size_t)(kk + k) * Kout + j0 + jq];
        }
        __syncthreads();

        #pragma unroll 8
        for (int k = 0; k < 64; k++) {
            float4 a = *(const float4*)&sxT[k * SXP + rg];
            float2 b = *(const float2*)&sw[k * SWP + cg];
            acc[0][0] += a.x * b.x; acc[0][1] += a.x * b.y;
            acc[1][0] += a.y * b.x; acc[1][1] += a.y * b.y;
            acc[2][0] += a.z * b.x; acc[2][1] += a.z * b.y;
            acc[3][0] += a.w * b.x; acc[3][1] += a.w * b.y;
        }
        __syncthreads();
    }

    #pragma unroll
    for (int i = 0; i < 4; i++) {
        int row = r0 + rg + i;
        if (row < NN) {
            float2 o = {acc[i][0], acc[i][1]};
            *(float2*)&Y[(size_t)row * Kout + j0 + cg] = o;
        }
    }
}

// ================= alpha dots: warp per node ===================================
template<int HH>
__global__ void alpha_kernel(const float* __restrict__ h,
                             const float* __restrict__ as_,
                             const float* __restrict__ ad_) {
    int warp = (blockIdx.x * blockDim.x + threadIdx.x) >> 5;
    int lane = threadIdx.x & 31;
    if (warp >= NN) return;
    if constexpr (HH == 4) {
        float4 v = *(const float4*)&h[(size_t)warp * 128 + lane * 4];
        int hh = lane >> 3;
        int c0 = (lane & 7) * 4;
        float4 a = *(const float4*)&as_[hh * 32 + c0];
        float4 b = *(const float4*)&ad_[hh * 32 + c0];
        float s = v.x * a.x + v.y * a.y + v.z * a.z + v.w * a.w;
        float d = v.x * b.x + v.y * b.y + v.z * b.z + v.w * b.w;
        #pragma unroll
        for (int o = 4; o >= 1; o >>= 1) {
            s += __shfl_xor_sync(FULL, s, o);
            d += __shfl_xor_sync(FULL, d, o);
        }
        if ((lane & 7) == 0) { g_as[warp * 4 + hh] = s; g_ad[warp * 4 + hh] = d; }
    } else {
        float v = h[(size_t)warp * 32 + lane];
        float s = v * as_[lane], d = v * ad_[lane];
        #pragma unroll
        for (int o = 16; o >= 1; o >>= 1) {
            s += __shfl_xor_sync(FULL, s, o);
            d += __shfl_xor_sync(FULL, d, o);
        }
        if (lane == 0) { g_as[warp] = s; g_ad[warp] = d; }
    }
}

// ================= segment softmax over in-edges: warp per node ================
__device__ __forceinline__ float leaky(float x) { return x > 0.0f ? x : 0.2f * x; }

template<int HH>
__global__ void csr_softmax() {
    int warp = (blockIdx.x * blockDim.x + threadIdx.x) >> 5;
    int lane = threadIdx.x & 31;
    if (warp >= NN) return;
    int off = g_rowptr[warp];
    int deg = g_rowptr[warp + 1] - off;

    if constexpr (HH == 4) {
        float4 adv = *(const float4*)&g_ad[warp * 4];
        float mx = -1e30f, my = -1e30f, mz = -1e30f, mw = -1e30f;
        for (int e = lane; e < deg; e += 32) {
            int s = g_csrc[off + e];
            float4 a = *(const float4*)&g_as[s * 4];
            mx = fmaxf(mx, a.x); my = fmaxf(my, a.y);
            mz = fmaxf(mz, a.z); mw = fmaxf(mw, a.w);
        }
        #pragma unroll
        for (int o = 16; o >= 1; o >>= 1) {
            mx = fmaxf(mx, __shfl_xor_sync(FULL, mx, o));
            my = fmaxf(my, __shfl_xor_sync(FULL, my, o));
            mz = fmaxf(mz, __shfl_xor_sync(FULL, mz, o));
            mw = fmaxf(mw, __shfl_xor_sync(FULL, mw, o));
        }
        // leaky is monotone increasing and ad is constant per node:
        // max_e leaky(as_e + ad) = leaky(max_e as_e + ad)
        mx = leaky(mx + adv.x); my = leaky(my + adv.y);
        mz = leaky(mz + adv.z); mw = leaky(mw + adv.w);
        float dx = 0, dy = 0, dz = 0, dw = 0;
        for (int e = lane; e < deg; e += 32) {
            int s = g_csrc[off + e];
            float4 a = *(const float4*)&g_as[s * 4];
            float4 ex;
            ex.x = __expf(leaky(a.x + adv.x) - mx);
            ex.y = __expf(leaky(a.y + adv.y) - my);
            ex.z = __expf(leaky(a.z + adv.z) - mz);
            ex.w = __expf(leaky(a.w + adv.w) - mw);
            *(float4*)&g_e[(size_t)(off + e) * 4] = ex;
            dx += ex.x; dy += ex.y; dz += ex.z; dw += ex.w;
        }
        #pragma unroll
        for (int o = 16; o >= 1; o >>= 1) {
            dx += __shfl_xor_sync(FULL, dx, o);
            dy += __shfl_xor_sync(FULL, dy, o);
            dz += __shfl_xor_sync(FULL, dz, o);
            dw += __shfl_xor_sync(FULL, dw, o);
        }
        if (lane == 0) {
            float4 dn = {dx, dy, dz, dw};
            *(float4*)&g_den[warp * 4] = dn;
        }
    } else {
        float adv = g_ad[warp];
        float m = -1e30f;
        for (int e = lane; e < deg; e += 32)
            m = fmaxf(m, g_as[g_csrc[off + e]]);
        #pragma unroll
        for (int o = 16; o >= 1; o >>= 1) m = fmaxf(m, __shfl_xor_sync(FULL, m, o));
        m = leaky(m + adv);
        float dsum = 0;
        for (int e = lane; e < deg; e += 32) {
            float ex = __expf(leaky(g_as[g_csrc[off + e]] + adv) - m);
            g_e[off + e] = ex;
            dsum += ex;
        }
        #pragma unroll
        for (int o = 16; o >= 1; o >>= 1) dsum += __shfl_xor_sync(FULL, dsum, o);
        if (lane == 0) g_den[warp] = dsum;
    }
}

// ================= pull aggregation: ONE warp per node, full row ===============
// lane owns 4 channels (float4); head = lane>>3. Per edge: one 512B row gather.
template<int HH>
__global__ void csr_aggregate(const float* __restrict__ hf,
                              const float* __restrict__ bias) {
    int n = (blockIdx.x * blockDim.x + threadIdx.x) >> 5;
    int lane = threadIdx.x & 31;
    if (n >= NN) return;
    int off = g_rowptr[n];
    int deg = g_rowptr[n + 1] - off;

    if constexpr (HH == 4) {
        const int head = lane >> 3;
        float4 acc = {0.0f, 0.0f, 0.0f, 0.0f};
        for (int base = 0; base < deg; base += 32) {
            int e = base + lane;
            int s = 0;
            float4 w = {0, 0, 0, 0};
            if (e < deg) {
                int p = off + e;
                s = g_csrc[p];
                w = *(const float4*)&g_e[(size_t)p * 4];
            }
            int cnt = min(32, deg - base);
            #pragma unroll 4
            for (int j = 0; j < cnt; j++) {
                int   sj = __shfl_sync(FULL, s, j);
                float w0 = __shfl_sync(FULL, w.x, j);
                float w1 = __shfl_sync(FULL, w.y, j);
                float w2 = __shfl_sync(FULL, w.z, j);
                float w3 = __shfl_sync(FULL, w.w, j);
                float ws = head == 0 ? w0 : head == 1 ? w1 : head == 2 ? w2 : w3;
                float4 v = *(const float4*)&hf[(size_t)sj * 128 + lane * 4];
                acc.x += ws * v.x; acc.y += ws * v.y;
                acc.z += ws * v.z; acc.w += ws * v.w;
            }
        }
        float inv = 1.0f / (g_den[n * 4 + head] + 1e-16f);
        float4 bv = *(const float4*)&bias[lane * 4];
        float4 o;
        o.x = fmaxf(acc.x * inv + bv.x, 0.0f);
        o.y = fmaxf(acc.y * inv + bv.y, 0.0f);
        o.z = fmaxf(acc.z * inv + bv.z, 0.0f);
        o.w = fmaxf(acc.w * inv + bv.w, 0.0f);
        *(float4*)&g_feat[(size_t)n * 128 + lane * 4] = o;
    } else {
        float acc = 0.0f;
        for (int base = 0; base < deg; base += 32) {
            int e = base + lane;
            int s = 0; float w = 0.0f;
            if (e < deg) {
                int p = off + e;
                s = g_csrc[p];
                w = g_e[p];
            }
            int cnt = min(32, deg - base);
            #pragma unroll 4
            for (int j = 0; j < cnt; j++) {
                int   sj = __shfl_sync(FULL, s, j);
                float wj = __shfl_sync(FULL, w, j);
                acc += wj * hf[(size_t)sj * 32 + lane];
            }
        }
        float inv = 1.0f / (g_den[n] + 1e-16f);
        float v = acc * inv + bias[lane];
        g_feat[(size_t)n * 32 + lane] = v > 0.0f ? v : 0.0f;
    }
}

// ================= final linear 32 -> 40 =======================================
__global__ void final_linear(const float* __restrict__ xin,
                             const float* __restrict__ w,
                             const float* __restrict__ b,
                             float* __restrict__ out) {
    __shared__ float swt[32 * 40];
    __shared__ float sxr[64 * 33];
    int tid = threadIdx.x;
    int n0 = blockIdx.x * 64;
    for (int i = tid; i < 32 * 40; i += 256) swt[i] = w[i];
    for (int i = tid; i < 64 * 32; i += 256) {
        int n = i >> 5, c = i & 31;
        int gn = n0 + n;
        sxr[n * 33 + c] = (gn < NN) ? xin[(size_t)gn * 32 + c] : 0.0f;
    }
    __syncthreads();
    int nl = tid >> 2;
    int j0 = (tid & 3) * 10;
    int gn = n0 + nl;
    if (gn >= NN) return;
    float acc[10];
    #pragma unroll
    for (int j = 0; j < 10; j++) acc[j] = b[j0 + j];
    #pragma unroll
    for (int k = 0; k < 32; k++) {
        float xv = sxr[nl * 33 + k];
        #pragma unroll
        for (int j = 0; j < 10; j++) acc[j] += xv * swt[k * 40 + j0 + j];
    }
    #pragma unroll
    for (int j = 0; j < 10; j++) out[(size_t)gn * 40 + j0 + j] = acc[j];
}

// ================= launch ======================================================
extern "C" void kernel_launch(void* const* d_in, const int* in_sizes, int n_in,
                              void* d_out, int out_size) {
    const float* x   = (const float*)d_in[0];
    const int*   ei  = (const int*)d_in[1];
    const float* W0  = (const float*)d_in[2];
    const float* as0 = (const float*)d_in[3];
    const float* ad0 = (const float*)d_in[4];
    const float* b0  = (const float*)d_in[5];
    const float* W1  = (const float*)d_in[6];
    const float* as1 = (const float*)d_in[7];
    const float* ad1 = (const float*)d_in[8];
    const float* b1  = (const float*)d_in[9];
    const float* W2  = (const float*)d_in[10];
    const float* as2 = (const float*)d_in[11];
    const float* ad2 = (const float*)d_in[12];
    const float* b2  = (const float*)d_in[13];
    const float* lw  = (const float*)d_in[14];
    const float* lb  = (const float*)d_in[15];
    float* out = (float*)d_out;

    float *p_h, *p_feat;
    cudaGetSymbolAddress((void**)&p_h,    g_h);
    cudaGetSymbolAddress((void**)&p_feat, g_feat);

    const int T = 256;
    const int WPB = T / 32;   // warps per block

    // ---- CSR build (once) ----
    detect_dtype<<<1, 32>>>(ei);
    clear_deg<<<cdiv(NN, T), T>>>();
    build_edges<<<cdiv(ETOT, T), T>>>(ei);
    scan_a<<<NB, 256>>>();
    scan_b<<<1, 32>>>();
    scan_c<<<NB, 256>>>();
    scatter_csr<<<cdiv(ETOT, T), T>>>();

    // ---- layer 0: 128 -> 4x32, concat ----
    gemm_big<<<cdiv(NN, 64), 128>>>(x, W0, p_h);
    alpha_kernel<4><<<cdiv(NN, WPB), T>>>(p_h, as0, ad0);
    csr_softmax<4><<<cdiv(NN, WPB), T>>>();
    csr_aggregate<4><<<cdiv(NN, WPB), T>>>(p_h, b0);

    // ---- layer 1: 128 -> 4x32, concat ----
    gemm_big<<<cdiv(NN, 64), 128>>>(p_feat, W1, p_h);
    alpha_kernel<4><<<cdiv(NN, WPB), T>>>(p_h, as1, ad1);
    csr_softmax<4><<<cdiv(NN, WPB), T>>>();
    csr_aggregate<4><<<cdiv(NN, WPB), T>>>(p_h, b1);

    // ---- layer 2: 128 -> 32, heads=1, mean(=identity) ----
    gemm64<32, 2><<<dim3(cdiv(NN, 64), 1), T>>>(p_feat, W2, p_h, 32);
    alpha_kernel<1><<<cdiv(NN, WPB), T>>>(p_h, as2, ad2);
    csr_softmax<1><<<cdiv(NN, WPB), T>>>();
    csr_aggregate<1><<<cdiv(NN, WPB), T>>>(p_h, b2);

    // ---- final linear 32 -> 40 ----
    final_linear<<<cdiv(NN, 64), T>>>(p_feat, lw, lb, out);
}

// round 6
// speedup vs baseline: 1.6409x; 1.6409x over previous
#include <cuda_runtime.h>

#define NN 100000
#define EE 1600000
#define ETOT (EE + NN)      // edges + self loops
#define FH 128              // heads*channels for layers 0/1
#define CC 32               // channels per head
#define NCLS 40
#define FULL 0xffffffffu

// ---------------- scratch (device globals; no allocation allowed) ------------
__device__ __align__(16) float g_h[NN * FH];      // transformed features (x @ W)
__device__ __align__(16) float g_feat[NN * FH];   // layer output features
__device__ __align__(16) float g_e[(size_t)ETOT * 4];   // per-edge per-head exp weights (CSR order)
__device__ __align__(16) float g_as[NN * 4];
__device__ __align__(16) float g_ad[NN * 4];
__device__ __align__(16) float g_den[NN * 4];
__device__ int   g_src[ETOT];
__device__ int   g_dst[ETOT];
__device__ int   g_csrc[ETOT];        // CSR: src per edge, grouped by dst
__device__ int   g_deg[NN];
__device__ int   g_rowptr[NN + 1];
__device__ int   g_cursor[NN];
__device__ int   g_bsum[128];
__device__ int   g_boff[128];
__device__ int   g_is64;

#define SCAN_CHUNK 1024
#define NB ((NN + SCAN_CHUNK - 1) / SCAN_CHUNK)   // 98

static inline int cdiv(int a, int b) { return (a + b - 1) / b; }

// ================= edge ingestion + CSR build =================================
__global__ void detect_dtype(const int* __restrict__ e) {
    if (blockIdx.x != 0 || threadIdx.x != 0) return;
    int any = 0;
    for (int i = 0; i < 4096; i++) any |= e[2 * i + 1];
    g_is64 = (any == 0) ? 1 : 0;
}

__global__ void clear_deg() {
    int i = blockIdx.x * blockDim.x + threadIdx.x;
    if (i < NN) g_deg[i] = 0;
}

__global__ void build_edges(const int* __restrict__ e) {
    int i = blockIdx.x * blockDim.x + threadIdx.x;
    if (i >= ETOT) return;
    int s, d;
    if (i < EE) {
        if (g_is64) { s = e[2 * (size_t)i]; d = e[2 * ((size_t)EE + i)]; }
        else        { s = e[i];             d = e[EE + i]; }
    } else {
        s = i - EE; d = i - EE;
    }
    g_src[i] = s;
    g_dst[i] = d;
    atomicAdd(&g_deg[d], 1);
}

__global__ void scan_a() {
    __shared__ int sm[256];
    int blk = blockIdx.x, tid = threadIdx.x;
    int base = blk * SCAN_CHUNK + tid * 4;
    int t = 0;
    #pragma unroll
    for (int i = 0; i < 4; i++) if (base + i < NN) t += g_deg[base + i];
    sm[tid] = t;
    __syncthreads();
    for (int o = 128; o > 0; o >>= 1) {
        if (tid < o) sm[tid] += sm[tid + o];
        __syncthreads();
    }
    if (tid == 0) g_bsum[blk] = sm[0];
}

__global__ void scan_b() {
    if (threadIdx.x != 0) return;
    int run = 0;
    for (int i = 0; i < NB; i++) { g_boff[i] = run; run += g_bsum[i]; }
}

__global__ void scan_c() {
    int blk = blockIdx.x, tid = threadIdx.x;
    int base = blk * SCAN_CHUNK + tid * 4;
    int v[4];
    #pragma unroll
    for (int i = 0; i < 4; i++) v[i] = (base + i < NN) ? g_deg[base + i] : 0;
    int tsum = v[0] + v[1] + v[2] + v[3];
    int lane = tid & 31, wid = tid >> 5;
    int inc = tsum;
    #pragma unroll
    for (int o = 1; o < 32; o <<= 1) {
        int t = __shfl_up_sync(FULL, inc, o);
        if (lane >= o) inc += t;
    }
    __shared__ int wsum[8];
    if (lane == 31) wsum[wid] = inc;
    __syncthreads();
    if (tid < 8) {
        int t = wsum[tid];
        #pragma unroll
        for (int o = 1; o < 8; o <<= 1) {
            int u = __shfl_up_sync(0xff, t, o);
            if (tid >= o) t += u;
        }
        wsum[tid] = t;
    }
    __syncthreads();
    int excl = inc - tsum + (wid > 0 ? wsum[wid - 1] : 0) + g_boff[blk];
    #pragma unroll
    for (int i = 0; i < 4; i++) {
        if (base + i < NN) { g_rowptr[base + i] = excl; g_cursor[base + i] = excl; }
        excl += v[i];
    }
    if (blk == 0 && tid == 0) g_rowptr[NN] = ETOT;
}

__global__ void scatter_csr() {
    int i = blockIdx.x * blockDim.x + threadIdx.x;
    if (i >= ETOT) return;
    int pos = atomicAdd(&g_cursor[g_dst[i]], 1);
    g_csrc[pos] = g_src[i];
}

// ================= GEMM (big): Y[N,128] = X[N,128] @ W[128,128] ================
// 256 threads, BM=128, BN=128, 8x8 per thread, k staged in chunks of 32.
__global__ void gemm_big(const float* __restrict__ X, const float* __restrict__ W,
                         float* __restrict__ Y) {
    __shared__ __align__(16) float sxT[32 * 132];   // [k][row]
    __shared__ __align__(16) float sw[32 * 132];    // [k][col]
    const int tid = threadIdx.x;
    const int r0 = blockIdx.x * 128;
    const int rg = (tid >> 4) * 8;     // 16 row groups
    const int cg = (tid & 15) * 8;     // 16 col groups

    float acc[8][8];
    #pragma unroll
    for (int i = 0; i < 8; i++)
        #pragma unroll
        for (int j = 0; j < 8; j++) acc[i][j] = 0.0f;

    for (int kk = 0; kk < 128; kk += 32) {
        // X tile: 128 rows x 32 k, float4 loads, transposed store
        #pragma unroll
        for (int it = 0; it < 4; it++) {
            int idx = tid + it * 256;          // [0,1024)
            int row = idx >> 3;                // 0..127
            int kq  = idx & 7;                 // 0..7
            int grow = r0 + row; if (grow >= NN) grow = NN - 1;
            float4 v = *(const float4*)&X[(size_t)grow * 128 + kk + kq * 4];
            sxT[(kq * 4 + 0) * 132 + row] = v.x;
            sxT[(kq * 4 + 1) * 132 + row] = v.y;
            sxT[(kq * 4 + 2) * 132 + row] = v.z;
            sxT[(kq * 4 + 3) * 132 + row] = v.w;
        }
        // W tile: 32 k x 128 cols, float4
        #pragma unroll
        for (int it = 0; it < 4; it++) {
            int idx = tid + it * 256;          // [0,1024)
            int k  = idx >> 5;
            int cq = idx & 31;
            *(float4*)&sw[k * 132 + cq * 4] =
                *(const float4*)&W[(size_t)(kk + k) * 128 + cq * 4];
        }
        __syncthreads();

        #pragma unroll
        for (int k = 0; k < 32; k++) {
            float4 a0 = *(const float4*)&sxT[k * 132 + rg];
            float4 a1 = *(const float4*)&sxT[k * 132 + rg + 4];
            float4 b0 = *(const float4*)&sw[k * 132 + cg];
            float4 b1 = *(const float4*)&sw[k * 132 + cg + 4];
            float ar[8] = {a0.x, a0.y, a0.z, a0.w, a1.x, a1.y, a1.z, a1.w};
            float bc[8] = {b0.x, b0.y, b0.z, b0.w, b1.x, b1.y, b1.z, b1.w};
            #pragma unroll
            for (int i = 0; i < 8; i++)
                #pragma unroll
                for (int j = 0; j < 8; j++)
                    acc[i][j] += ar[i] * bc[j];
        }
        __syncthreads();
    }

    #pragma unroll
    for (int i = 0; i < 8; i++) {
        int row = r0 + rg + i;
        if (row < NN) {
            float4 o0 = {acc[i][0], acc[i][1], acc[i][2], acc[i][3]};
            float4 o1 = {acc[i][4], acc[i][5], acc[i][6], acc[i][7]};
            *(float4*)&Y[(size_t)row * 128 + cg]     = o0;
            *(float4*)&Y[(size_t)row * 128 + cg + 4] = o1;
        }
    }
}

// ================= GEMM (small): Y[N,32] = X[N,128] @ W[128,32] ================
template<int BN, int TN>
__global__ void gemm64(const float* __restrict__ X, const float* __restrict__ W,
                       float* __restrict__ Y, int Kout) {
    constexpr int SXP = 68;
    constexpr int SWP = BN + 4;
    __shared__ __align__(16) float sxT[64 * SXP];
    __shared__ __align__(16) float sw[64 * SWP];
    const int tid = threadIdx.x;
    const int r0 = blockIdx.x * 64;
    const int j0 = blockIdx.y * BN;

    const int rg = (tid >> 4) * 4;
    const int cg = (tid & 15) * TN;
    float acc[4][TN];
    #pragma unroll
    for (int i = 0; i < 4; i++)
        #pragma unroll
        for (int j = 0; j < TN; j++) acc[i][j] = 0.0f;

    for (int kk = 0; kk < 128; kk += 64) {
        for (int idx = tid; idx < 64 * 64; idx += 256) {
            int k = idx & 63;
            int r = idx >> 6;
            int row = r0 + r; if (row >= NN) row = NN - 1;
            sxT[k * SXP + r] = X[(size_t)row * 128 + kk + k];
        }
        for (int idx = tid; idx < 64 * BN / 4; idx += 256) {
            int k = idx / (BN / 4);
            int jq = (idx % (BN / 4)) * 4;
            *(float4*)&sw[k * SWP + jq] =
                *(const float4*)&W[(size_t)(kk + k) * Kout + j0 + jq];
        }
        __syncthreads();

        #pragma unroll 8
        for (int k = 0; k < 64; k++) {
            float4 a = *(const float4*)&sxT[k * SXP + rg];
            float2 b = *(const float2*)&sw[k * SWP + cg];
            acc[0][0] += a.x * b.x; acc[0][1] += a.x * b.y;
            acc[1][0] += a.y * b.x; acc[1][1] += a.y * b.y;
            acc[2][0] += a.z * b.x; acc[2][1] += a.z * b.y;
            acc[3][0] += a.w * b.x; acc[3][1] += a.w * b.y;
        }
        __syncthreads();
    }

    #pragma unroll
    for (int i = 0; i < 4; i++) {
        int row = r0 + rg + i;
        if (row < NN) {
            float2 o = {acc[i][0], acc[i][1]};
            *(float2*)&Y[(size_t)row * Kout + j0 + cg] = o;
        }
    }
}

// ================= alpha dots: warp per node ===================================
template<int HH>
__global__ void alpha_kernel(const float* __restrict__ h,
                             const float* __restrict__ as_,
                             const float* __restrict__ ad_) {
    int warp = (blockIdx.x * blockDim.x + threadIdx.x) >> 5;
    int lane = threadIdx.x & 31;
    if (warp >= NN) return;
    if constexpr (HH == 4) {
        float4 v = *(const float4*)&h[(size_t)warp * 128 + lane * 4];
        int hh = lane >> 3;
        int c0 = (lane & 7) * 4;
        float4 a = *(const float4*)&as_[hh * 32 + c0];
        float4 b = *(const float4*)&ad_[hh * 32 + c0];
        float s = v.x * a.x + v.y * a.y + v.z * a.z + v.w * a.w;
        float d = v.x * b.x + v.y * b.y + v.z * b.z + v.w * b.w;
        #pragma unroll
        for (int o = 4; o >= 1; o >>= 1) {
            s += __shfl_xor_sync(FULL, s, o);
            d += __shfl_xor_sync(FULL, d, o);
        }
        if ((lane & 7) == 0) { g_as[warp * 4 + hh] = s; g_ad[warp * 4 + hh] = d; }
    } else {
        float v = h[(size_t)warp * 32 + lane];
        float s = v * as_[lane], d = v * ad_[lane];
        #pragma unroll
        for (int o = 16; o >= 1; o >>= 1) {
            s += __shfl_xor_sync(FULL, s, o);
            d += __shfl_xor_sync(FULL, d, o);
        }
        if (lane == 0) { g_as[warp] = s; g_ad[warp] = d; }
    }
}

// ================= segment softmax over in-edges: warp per node ================
__device__ __forceinline__ float leaky(float x) { return x > 0.0f ? x : 0.2f * x; }

template<int HH>
__global__ void csr_softmax() {
    int warp = (blockIdx.x * blockDim.x + threadIdx.x) >> 5;
    int lane = threadIdx.x & 31;
    if (warp >= NN) return;
    int off = g_rowptr[warp];
    int deg = g_rowptr[warp + 1] - off;

    if constexpr (HH == 4) {
        float4 adv = *(const float4*)&g_ad[warp * 4];
        float mx = -1e30f, my = -1e30f, mz = -1e30f, mw = -1e30f;
        for (int e = lane; e < deg; e += 32) {
            int s = g_csrc[off + e];
            float4 a = *(const float4*)&g_as[s * 4];
            mx = fmaxf(mx, a.x); my = fmaxf(my, a.y);
            mz = fmaxf(mz, a.z); mw = fmaxf(mw, a.w);
        }
        #pragma unroll
        for (int o = 16; o >= 1; o >>= 1) {
            mx = fmaxf(mx, __shfl_xor_sync(FULL, mx, o));
            my = fmaxf(my, __shfl_xor_sync(FULL, my, o));
            mz = fmaxf(mz, __shfl_xor_sync(FULL, mz, o));
            mw = fmaxf(mw, __shfl_xor_sync(FULL, mw, o));
        }
        // leaky monotone + ad constant per node: max leaky(as+ad) = leaky(max as + ad)
        mx = leaky(mx + adv.x); my = leaky(my + adv.y);
        mz = leaky(mz + adv.z); mw = leaky(mw + adv.w);
        float dx = 0, dy = 0, dz = 0, dw = 0;
        for (int e = lane; e < deg; e += 32) {
            int s = g_csrc[off + e];
            float4 a = *(const float4*)&g_as[s * 4];
            float4 ex;
            ex.x = __expf(leaky(a.x + adv.x) - mx);
            ex.y = __expf(leaky(a.y + adv.y) - my);
            ex.z = __expf(leaky(a.z + adv.z) - mz);
            ex.w = __expf(leaky(a.w + adv.w) - mw);
            *(float4*)&g_e[(size_t)(off + e) * 4] = ex;
            dx += ex.x; dy += ex.y; dz += ex.z; dw += ex.w;
        }
        #pragma unroll
        for (int o = 16; o >= 1; o >>= 1) {
            dx += __shfl_xor_sync(FULL, dx, o);
            dy += __shfl_xor_sync(FULL, dy, o);
            dz += __shfl_xor_sync(FULL, dz, o);
            dw += __shfl_xor_sync(FULL, dw, o);
        }
        if (lane == 0) {
            float4 dn = {dx, dy, dz, dw};
            *(float4*)&g_den[warp * 4] = dn;
        }
    } else {
        float adv = g_ad[warp];
        float m = -1e30f;
        for (int e = lane; e < deg; e += 32)
            m = fmaxf(m, g_as[g_csrc[off + e]]);
        #pragma unroll
        for (int o = 16; o >= 1; o >>= 1) m = fmaxf(m, __shfl_xor_sync(FULL, m, o));
        m = leaky(m + adv);
        float dsum = 0;
        for (int e = lane; e < deg; e += 32) {
            float ex = __expf(leaky(g_as[g_csrc[off + e]] + adv) - m);
            g_e[off + e] = ex;
            dsum += ex;
        }
        #pragma unroll
        for (int o = 16; o >= 1; o >>= 1) dsum += __shfl_xor_sync(FULL, dsum, o);
        if (lane == 0) g_den[warp] = dsum;
    }
}

// ================= pull aggregation: ONE warp per node, no shuffles ============
// All lanes walk the edge list together: src index via warp-uniform load,
// weight via per-head sector load, then one coalesced 512B row gather.
template<int HH>
__global__ void csr_aggregate(const float* __restrict__ hf,
                              const float* __restrict__ bias) {
    int n = (blockIdx.x * blockDim.x + threadIdx.x) >> 5;
    int lane = threadIdx.x & 31;
    if (n >= NN) return;
    int off = g_rowptr[n];
    int end = g_rowptr[n + 1];

    if constexpr (HH == 4) {
        const int head = lane >> 3;
        float4 acc = {0.0f, 0.0f, 0.0f, 0.0f};
        #pragma unroll 4
        for (int p = off; p < end; p++) {
            int s = __ldg(&g_csrc[p]);                     // warp-uniform
            float w = __ldg(&g_e[(size_t)p * 4 + head]);   // 1 sector / warp
            const float4 v = *(const float4*)&hf[(size_t)s * 128 + lane * 4];
            acc.x += w * v.x; acc.y += w * v.y;
            acc.z += w * v.z; acc.w += w * v.w;
        }
        float inv = 1.0f / (g_den[n * 4 + head] + 1e-16f);
        float4 bv = *(const float4*)&bias[lane * 4];
        float4 o;
        o.x = fmaxf(acc.x * inv + bv.x, 0.0f);
        o.y = fmaxf(acc.y * inv + bv.y, 0.0f);
        o.z = fmaxf(acc.z * inv + bv.z, 0.0f);
        o.w = fmaxf(acc.w * inv + bv.w, 0.0f);
        *(float4*)&g_feat[(size_t)n * 128 + lane * 4] = o;
    } else {
        float acc = 0.0f;
        #pragma unroll 4
        for (int p = off; p < end; p++) {
            int s = __ldg(&g_csrc[p]);
            float w = __ldg(&g_e[p]);
            acc += w * hf[(size_t)s * 32 + lane];
        }
        float inv = 1.0f / (g_den[n] + 1e-16f);
        float v = acc * inv + bias[lane];
        g_feat[(size_t)n * 32 + lane] = v > 0.0f ? v : 0.0f;
    }
}

// ================= final linear 32 -> 40 =======================================
__global__ void final_linear(const float* __restrict__ xin,
                             const float* __restrict__ w,
                             const float* __restrict__ b,
                             float* __restrict__ out) {
    __shared__ float swt[32 * 40];
    __shared__ float sxr[64 * 33];
    int tid = threadIdx.x;
    int n0 = blockIdx.x * 64;
    for (int i = tid; i < 32 * 40; i += 256) swt[i] = w[i];
    for (int i = tid; i < 64 * 32; i += 256) {
        int n = i >> 5, c = i & 31;
        int gn = n0 + n;
        sxr[n * 33 + c] = (gn < NN) ? xin[(size_t)gn * 32 + c] : 0.0f;
    }
    __syncthreads();
    int nl = tid >> 2;
    int j0 = (tid & 3) * 10;
    int gn = n0 + nl;
    if (gn >= NN) return;
    float acc[10];
    #pragma unroll
    for (int j = 0; j < 10; j++) acc[j] = b[j0 + j];
    #pragma unroll
    for (int k = 0; k < 32; k++) {
        float xv = sxr[nl * 33 + k];
        #pragma unroll
        for (int j = 0; j < 10; j++) acc[j] += xv * swt[k * 40 + j0 + j];
    }
    #pragma unroll
    for (int j = 0; j < 10; j++) out[(size_t)gn * 40 + j0 + j] = acc[j];
}

// ================= launch ======================================================
extern "C" void kernel_launch(void* const* d_in, const int* in_sizes, int n_in,
                              void* d_out, int out_size) {
    const float* x   = (const float*)d_in[0];
    const int*   ei  = (const int*)d_in[1];
    const float* W0  = (const float*)d_in[2];
    const float* as0 = (const float*)d_in[3];
    const float* ad0 = (const float*)d_in[4];
    const float* b0  = (const float*)d_in[5];
    const float* W1  = (const float*)d_in[6];
    const float* as1 = (const float*)d_in[7];
    const float* ad1 = (const float*)d_in[8];
    const float* b1  = (const float*)d_in[9];
    const float* W2  = (const float*)d_in[10];
    const float* as2 = (const float*)d_in[11];
    const float* ad2 = (const float*)d_in[12];
    const float* b2  = (const float*)d_in[13];
    const float* lw  = (const float*)d_in[14];
    const float* lb  = (const float*)d_in[15];
    float* out = (float*)d_out;

    float *p_h, *p_feat;
    cudaGetSymbolAddress((void**)&p_h,    g_h);
    cudaGetSymbolAddress((void**)&p_feat, g_feat);

    const int T = 256;
    const int WPB = T / 32;   // warps per block

    // ---- CSR build (once) ----
    detect_dtype<<<1, 32>>>(ei);
    clear_deg<<<cdiv(NN, T), T>>>();
    build_edges<<<cdiv(ETOT, T), T>>>(ei);
    scan_a<<<NB, 256>>>();
    scan_b<<<1, 32>>>();
    scan_c<<<NB, 256>>>();
    scatter_csr<<<cdiv(ETOT, T), T>>>();

    // ---- layer 0: 128 -> 4x32, concat ----
    gemm_big<<<cdiv(NN, 128), 256>>>(x, W0, p_h);
    alpha_kernel<4><<<cdiv(NN, WPB), T>>>(p_h, as0, ad0);
    csr_softmax<4><<<cdiv(NN, WPB), T>>>();
    csr_aggregate<4><<<cdiv(NN, WPB), T>>>(p_h, b0);

    // ---- layer 1: 128 -> 4x32, concat ----
    gemm_big<<<cdiv(NN, 128), 256>>>(p_feat, W1, p_h);
    alpha_kernel<4><<<cdiv(NN, WPB), T>>>(p_h, as1, ad1);
    csr_softmax<4><<<cdiv(NN, WPB), T>>>();
    csr_aggregate<4><<<cdiv(NN, WPB), T>>>(p_h, b1);

    // ---- layer 2: 128 -> 32, heads=1, mean(=identity) ----
    gemm64<32, 2><<<dim3(cdiv(NN, 64), 1), T>>>(p_feat, W2, p_h, 32);
    alpha_kernel<1><<<cdiv(NN, WPB), T>>>(p_h, as2, ad2);
    csr_softmax<1><<<cdiv(NN, WPB), T>>>();
    csr_aggregate<1><<<cdiv(NN, WPB), T>>>(p_h, b2);

    // ---- final linear 32 -> 40 ----
    final_linear<<<cdiv(NN, 64), T>>>(p_feat, lw, lb, out);
}

// round 7
// speedup vs baseline: 1.7818x; 1.0859x over previous
#include <cuda_runtime.h>

#define NN 100000
#define EE 1600000
#define ETOT (EE + NN)      // edges + self loops
#define FH 128              // heads*channels for layers 0/1
#define CC 32               // channels per head
#define NCLS 40
#define FULL 0xffffffffu

// ---------------- scratch (device globals; no allocation allowed) ------------
__device__ __align__(16) float g_h[NN * FH];      // transformed features (x @ W)
__device__ __align__(16) float g_feat[NN * FH];   // layer output features
__device__ __align__(16) float g_e[(size_t)ETOT * 4];   // per-edge per-head exp weights (CSR order)
__device__ __align__(16) float g_as[NN * 4];
__device__ __align__(16) float g_ad[NN * 4];
__device__ __align__(16) float g_den[NN * 4];
__device__ int   g_src[ETOT];
__device__ int   g_dst[ETOT];
__device__ int   g_csrc[ETOT];        // CSR: src per edge, grouped by dst
__device__ int   g_deg[NN];
__device__ int   g_rowptr[NN + 1];
__device__ int   g_cursor[NN];
__device__ int   g_bsum[128];
__device__ int   g_boff[128];
__device__ int   g_is64;

#define SCAN_CHUNK 1024
#define NB ((NN + SCAN_CHUNK - 1) / SCAN_CHUNK)   // 98

static inline int cdiv(int a, int b) { return (a + b - 1) / b; }

// ================= edge ingestion + CSR build =================================
__global__ void detect_dtype(const int* __restrict__ e) {
    if (blockIdx.x != 0 || threadIdx.x != 0) return;
    int any = 0;
    for (int i = 0; i < 4096; i++) any |= e[2 * i + 1];
    g_is64 = (any == 0) ? 1 : 0;
}

__global__ void clear_deg() {
    int i = blockIdx.x * blockDim.x + threadIdx.x;
    if (i < NN) g_deg[i] = 0;
}

__global__ void build_edges(const int* __restrict__ e) {
    int i = blockIdx.x * blockDim.x + threadIdx.x;
    if (i >= ETOT) return;
    int s, d;
    if (i < EE) {
        if (g_is64) { s = e[2 * (size_t)i]; d = e[2 * ((size_t)EE + i)]; }
        else        { s = e[i];             d = e[EE + i]; }
    } else {
        s = i - EE; d = i - EE;
    }
    g_src[i] = s;
    g_dst[i] = d;
    atomicAdd(&g_deg[d], 1);
}

__global__ void scan_a() {
    __shared__ int sm[256];
    int blk = blockIdx.x, tid = threadIdx.x;
    int base = blk * SCAN_CHUNK + tid * 4;
    int t = 0;
    #pragma unroll
    for (int i = 0; i < 4; i++) if (base + i < NN) t += g_deg[base + i];
    sm[tid] = t;
    __syncthreads();
    for (int o = 128; o > 0; o >>= 1) {
        if (tid < o) sm[tid] += sm[tid + o];
        __syncthreads();
    }
    if (tid == 0) g_bsum[blk] = sm[0];
}

__global__ void scan_b() {
    if (threadIdx.x != 0) return;
    int run = 0;
    for (int i = 0; i < NB; i++) { g_boff[i] = run; run += g_bsum[i]; }
}

__global__ void scan_c() {
    int blk = blockIdx.x, tid = threadIdx.x;
    int base = blk * SCAN_CHUNK + tid * 4;
    int v[4];
    #pragma unroll
    for (int i = 0; i < 4; i++) v[i] = (base + i < NN) ? g_deg[base + i] : 0;
    int tsum = v[0] + v[1] + v[2] + v[3];
    int lane = tid & 31, wid = tid >> 5;
    int inc = tsum;
    #pragma unroll
    for (int o = 1; o < 32; o <<= 1) {
        int t = __shfl_up_sync(FULL, inc, o);
        if (lane >= o) inc += t;
    }
    __shared__ int wsum[8];
    if (lane == 31) wsum[wid] = inc;
    __syncthreads();
    if (tid < 8) {
        int t = wsum[tid];
        #pragma unroll
        for (int o = 1; o < 8; o <<= 1) {
            int u = __shfl_up_sync(0xff, t, o);
            if (tid >= o) t += u;
        }
        wsum[tid] = t;
    }
    __syncthreads();
    int excl = inc - tsum + (wid > 0 ? wsum[wid - 1] : 0) + g_boff[blk];
    #pragma unroll
    for (int i = 0; i < 4; i++) {
        if (base + i < NN) { g_rowptr[base + i] = excl; g_cursor[base + i] = excl; }
        excl += v[i];
    }
    if (blk == 0 && tid == 0) g_rowptr[NN] = ETOT;
}

__global__ void scatter_csr() {
    int i = blockIdx.x * blockDim.x + threadIdx.x;
    if (i >= ETOT) return;
    int pos = atomicAdd(&g_cursor[g_dst[i]], 1);
    g_csrc[pos] = g_src[i];
}

// ================= GEMM (big) + fused alpha =====================================
// Y[N,128] = X[N,128] @ W[128,128]; also writes g_as/g_ad per (row, head).
// 256 threads, BM=128, BN=128, 8x8 per thread, k staged in chunks of 32.
__global__ void gemm_big(const float* __restrict__ X, const float* __restrict__ W,
                         float* __restrict__ Y,
                         const float* __restrict__ as_, const float* __restrict__ ad_) {
    __shared__ __align__(16) float sxT[32 * 132];   // [k][row]
    __shared__ __align__(16) float sw[32 * 132];    // [k][col]
    const int tid = threadIdx.x;
    const int r0 = blockIdx.x * 128;
    const int rg = (tid >> 4) * 8;     // 16 row groups
    const int cg = (tid & 15) * 8;     // 16 col groups

    float acc[8][8];
    #pragma unroll
    for (int i = 0; i < 8; i++)
        #pragma unroll
        for (int j = 0; j < 8; j++) acc[i][j] = 0.0f;

    for (int kk = 0; kk < 128; kk += 32) {
        #pragma unroll
        for (int it = 0; it < 4; it++) {
            int idx = tid + it * 256;
            int row = idx >> 3;
            int kq  = idx & 7;
            int grow = r0 + row; if (grow >= NN) grow = NN - 1;
            float4 v = *(const float4*)&X[(size_t)grow * 128 + kk + kq * 4];
            sxT[(kq * 4 + 0) * 132 + row] = v.x;
            sxT[(kq * 4 + 1) * 132 + row] = v.y;
            sxT[(kq * 4 + 2) * 132 + row] = v.z;
            sxT[(kq * 4 + 3) * 132 + row] = v.w;
        }
        #pragma unroll
        for (int it = 0; it < 4; it++) {
            int idx = tid + it * 256;
            int k  = idx >> 5;
            int cq = idx & 31;
            *(float4*)&sw[k * 132 + cq * 4] =
                *(const float4*)&W[(size_t)(kk + k) * 128 + cq * 4];
        }
        __syncthreads();

        #pragma unroll
        for (int k = 0; k < 32; k++) {
            float4 a0 = *(const float4*)&sxT[k * 132 + rg];
            float4 a1 = *(const float4*)&sxT[k * 132 + rg + 4];
            float4 b0 = *(const float4*)&sw[k * 132 + cg];
            float4 b1 = *(const float4*)&sw[k * 132 + cg + 4];
            float ar[8] = {a0.x, a0.y, a0.z, a0.w, a1.x, a1.y, a1.z, a1.w};
            float bc[8] = {b0.x, b0.y, b0.z, b0.w, b1.x, b1.y, b1.z, b1.w};
            #pragma unroll
            for (int i = 0; i < 8; i++)
                #pragma unroll
                for (int j = 0; j < 8; j++)
                    acc[i][j] += ar[i] * bc[j];
        }
        __syncthreads();
    }

    // store Y tile
    #pragma unroll
    for (int i = 0; i < 8; i++) {
        int row = r0 + rg + i;
        if (row < NN) {
            float4 o0 = {acc[i][0], acc[i][1], acc[i][2], acc[i][3]};
            float4 o1 = {acc[i][4], acc[i][5], acc[i][6], acc[i][7]};
            *(float4*)&Y[(size_t)row * 128 + cg]     = o0;
            *(float4*)&Y[(size_t)row * 128 + cg + 4] = o1;
        }
    }

    // fused alpha: cols [cg, cg+8) lie inside head = cg>>5.
    // partial dot per row, then reduce across the 4 threads covering the head.
    float av[8], dv[8];
    #pragma unroll
    for (int j = 0; j < 8; j++) { av[j] = as_[cg + j]; dv[j] = ad_[cg + j]; }
    float ps[8], pd[8];
    #pragma unroll
    for (int i = 0; i < 8; i++) {
        float s = 0.0f, d = 0.0f;
        #pragma unroll
        for (int j = 0; j < 8; j++) { s += acc[i][j] * av[j]; d += acc[i][j] * dv[j]; }
        ps[i] = s; pd[i] = d;
    }
    // threads sharing rg differ only in (tid&15); head group = 4 consecutive.
    #pragma unroll
    for (int i = 0; i < 8; i++) {
        ps[i] += __shfl_xor_sync(FULL, ps[i], 1);
        pd[i] += __shfl_xor_sync(FULL, pd[i], 1);
        ps[i] += __shfl_xor_sync(FULL, ps[i], 2);
        pd[i] += __shfl_xor_sync(FULL, pd[i], 2);
    }
    if ((tid & 3) == 0) {
        int head = (tid & 15) >> 2;
        #pragma unroll
        for (int i = 0; i < 8; i++) {
            int row = r0 + rg + i;
            if (row < NN) {
                g_as[row * 4 + head] = ps[i];
                g_ad[row * 4 + head] = pd[i];
            }
        }
    }
}

// ================= GEMM (small) + fused alpha: Y[N,32] = X @ W[128,32] =========
__global__ void gemm_small(const float* __restrict__ X, const float* __restrict__ W,
                           float* __restrict__ Y,
                           const float* __restrict__ as_, const float* __restrict__ ad_) {
    constexpr int SXP = 68;
    constexpr int SWP = 36;
    __shared__ __align__(16) float sxT[64 * SXP];
    __shared__ __align__(16) float sw[64 * SWP];
    const int tid = threadIdx.x;
    const int r0 = blockIdx.x * 64;

    const int rg = (tid >> 4) * 4;
    const int cg = (tid & 15) * 2;
    float acc[4][2];
    #pragma unroll
    for (int i = 0; i < 4; i++) { acc[i][0] = 0.0f; acc[i][1] = 0.0f; }

    for (int kk = 0; kk < 128; kk += 64) {
        for (int idx = tid; idx < 64 * 64; idx += 256) {
            int k = idx & 63;
            int r = idx >> 6;
            int row = r0 + r; if (row >= NN) row = NN - 1;
            sxT[k * SXP + r] = X[(size_t)row * 128 + kk + k];
        }
        for (int idx = tid; idx < 64 * 8; idx += 256) {
            int k = idx / 8;
            int jq = (idx % 8) * 4;
            *(float4*)&sw[k * SWP + jq] =
                *(const float4*)&W[(size_t)(kk + k) * 32 + jq];
        }
        __syncthreads();

        #pragma unroll 8
        for (int k = 0; k < 64; k++) {
            float4 a = *(const float4*)&sxT[k * SXP + rg];
            float2 b = *(const float2*)&sw[k * SWP + cg];
            acc[0][0] += a.x * b.x; acc[0][1] += a.x * b.y;
            acc[1][0] += a.y * b.x; acc[1][1] += a.y * b.y;
            acc[2][0] += a.z * b.x; acc[2][1] += a.z * b.y;
            acc[3][0] += a.w * b.x; acc[3][1] += a.w * b.y;
        }
        __syncthreads();
    }

    #pragma unroll
    for (int i = 0; i < 4; i++) {
        int row = r0 + rg + i;
        if (row < NN) {
            float2 o = {acc[i][0], acc[i][1]};
            *(float2*)&Y[(size_t)row * 32 + cg] = o;
        }
    }

    // fused alpha (single head): partial over 2 cols, reduce across 16 threads.
    float a0 = as_[cg], a1 = as_[cg + 1];
    float d0 = ad_[cg], d1 = ad_[cg + 1];
    float ps[4], pd[4];
    #pragma unroll
    for (int i = 0; i < 4; i++) {
        ps[i] = acc[i][0] * a0 + acc[i][1] * a1;
        pd[i] = acc[i][0] * d0 + acc[i][1] * d1;
    }
    #pragma unroll
    for (int o = 1; o < 16; o <<= 1) {
        #pragma unroll
        for (int i = 0; i < 4; i++) {
            ps[i] += __shfl_xor_sync(FULL, ps[i], o);
            pd[i] += __shfl_xor_sync(FULL, pd[i], o);
        }
    }
    if ((tid & 15) == 0) {
        #pragma unroll
        for (int i = 0; i < 4; i++) {
            int row = r0 + rg + i;
            if (row < NN) { g_as[row] = ps[i]; g_ad[row] = pd[i]; }
        }
    }
}

// ================= segment softmax: HALF-warp (16 lanes) per node ==============
__device__ __forceinline__ float leaky(float x) { return x > 0.0f ? x : 0.2f * x; }

template<int HH>
__global__ void csr_softmax() {
    int gt = blockIdx.x * blockDim.x + threadIdx.x;
    int node = gt >> 4;                 // 16 lanes per node
    int l16 = threadIdx.x & 15;
    int seg = (threadIdx.x >> 4) & 1;
    unsigned mask = 0xFFFFu << (seg * 16);
    if (node >= NN) return;
    int off = g_rowptr[node];
    int deg = g_rowptr[node + 1] - off;

    if constexpr (HH == 4) {
        float4 adv = *(const float4*)&g_ad[node * 4];
        float mx = -1e30f, my = -1e30f, mz = -1e30f, mw = -1e30f;
        for (int e = l16; e < deg; e += 16) {
            int s = g_csrc[off + e];
            float4 a = *(const float4*)&g_as[s * 4];
            mx = fmaxf(mx, a.x); my = fmaxf(my, a.y);
            mz = fmaxf(mz, a.z); mw = fmaxf(mw, a.w);
        }
        #pragma unroll
        for (int o = 8; o >= 1; o >>= 1) {
            mx = fmaxf(mx, __shfl_xor_sync(mask, mx, o));
            my = fmaxf(my, __shfl_xor_sync(mask, my, o));
            mz = fmaxf(mz, __shfl_xor_sync(mask, mz, o));
            mw = fmaxf(mw, __shfl_xor_sync(mask, mw, o));
        }
        mx = leaky(mx + adv.x); my = leaky(my + adv.y);
        mz = leaky(mz + adv.z); mw = leaky(mw + adv.w);
        float dx = 0, dy = 0, dz = 0, dw = 0;
        for (int e = l16; e < deg; e += 16) {
            int s = g_csrc[off + e];
            float4 a = *(const float4*)&g_as[s * 4];
            float4 ex;
            ex.x = __expf(leaky(a.x + adv.x) - mx);
            ex.y = __expf(leaky(a.y + adv.y) - my);
            ex.z = __expf(leaky(a.z + adv.z) - mz);
            ex.w = __expf(leaky(a.w + adv.w) - mw);
            *(float4*)&g_e[(size_t)(off + e) * 4] = ex;
            dx += ex.x; dy += ex.y; dz += ex.z; dw += ex.w;
        }
        #pragma unroll
        for (int o = 8; o >= 1; o >>= 1) {
            dx += __shfl_xor_sync(mask, dx, o);
            dy += __shfl_xor_sync(mask, dy, o);
            dz += __shfl_xor_sync(mask, dz, o);
            dw += __shfl_xor_sync(mask, dw, o);
        }
        if (l16 == 0) {
            float4 dn = {dx, dy, dz, dw};
            *(float4*)&g_den[node * 4] = dn;
        }
    } else {
        float adv = g_ad[node];
        float m = -1e30f;
        for (int e = l16; e < deg; e += 16)
            m = fmaxf(m, g_as[g_csrc[off + e]]);
        #pragma unroll
        for (int o = 8; o >= 1; o >>= 1) m = fmaxf(m, __shfl_xor_sync(mask, m, o));
        m = leaky(m + adv);
        float dsum = 0;
        for (int e = l16; e < deg; e += 16) {
            float ex = __expf(leaky(g_as[g_csrc[off + e]] + adv) - m);
            g_e[off + e] = ex;
            dsum += ex;
        }
        #pragma unroll
        for (int o = 8; o >= 1; o >>= 1) dsum += __shfl_xor_sync(mask, dsum, o);
        if (l16 == 0) g_den[node] = dsum;
    }
}

// ================= pull aggregation: ONE warp per node, no shuffles ============
template<int HH>
__global__ void csr_aggregate(const float* __restrict__ hf,
                              const float* __restrict__ bias) {
    int n = (blockIdx.x * blockDim.x + threadIdx.x) >> 5;
    int lane = threadIdx.x & 31;
    if (n >= NN) return;
    int off = g_rowptr[n];
    int end = g_rowptr[n + 1];

    if constexpr (HH == 4) {
        const int head = lane >> 3;
        float4 acc = {0.0f, 0.0f, 0.0f, 0.0f};
        #pragma unroll 4
        for (int p = off; p < end; p++) {
            int s = __ldg(&g_csrc[p]);                     // warp-uniform
            float w = __ldg(&g_e[(size_t)p * 4 + head]);   // 1 sector / warp
            const float4 v = *(const float4*)&hf[(size_t)s * 128 + lane * 4];
            acc.x += w * v.x; acc.y += w * v.y;
            acc.z += w * v.z; acc.w += w * v.w;
        }
        float inv = 1.0f / (g_den[n * 4 + head] + 1e-16f);
        float4 bv = *(const float4*)&bias[lane * 4];
        float4 o;
        o.x = fmaxf(acc.x * inv + bv.x, 0.0f);
        o.y = fmaxf(acc.y * inv + bv.y, 0.0f);
        o.z = fmaxf(acc.z * inv + bv.z, 0.0f);
        o.w = fmaxf(acc.w * inv + bv.w, 0.0f);
        *(float4*)&g_feat[(size_t)n * 128 + lane * 4] = o;
    } else {
        float acc = 0.0f;
        #pragma unroll 4
        for (int p = off; p < end; p++) {
            int s = __ldg(&g_csrc[p]);
            float w = __ldg(&g_e[p]);
            acc += w * hf[(size_t)s * 32 + lane];
        }
        float inv = 1.0f / (g_den[n] + 1e-16f);
        float v = acc * inv + bias[lane];
        g_feat[(size_t)n * 32 + lane] = v > 0.0f ? v : 0.0f;
    }
}

// ================= final linear 32 -> 40 =======================================
__global__ void final_linear(const float* __restrict__ xin,
                             const float* __restrict__ w,
                             const float* __restrict__ b,
                             float* __restrict__ out) {
    __shared__ float swt[32 * 40];
    __shared__ float sxr[64 * 33];
    int tid = threadIdx.x;
    int n0 = blockIdx.x * 64;
    for (int i = tid; i < 32 * 40; i += 256) swt[i] = w[i];
    for (int i = tid; i < 64 * 32; i += 256) {
        int n = i >> 5, c = i & 31;
        int gn = n0 + n;
        sxr[n * 33 + c] = (gn < NN) ? xin[(size_t)gn * 32 + c] : 0.0f;
    }
    __syncthreads();
    int nl = tid >> 2;
    int j0 = (tid & 3) * 10;
    int gn = n0 + nl;
    if (gn >= NN) return;
    float acc[10];
    #pragma unroll
    for (int j = 0; j < 10; j++) acc[j] = b[j0 + j];
    #pragma unroll
    for (int k = 0; k < 32; k++) {
        float xv = sxr[nl * 33 + k];
        #pragma unroll
        for (int j = 0; j < 10; j++) acc[j] += xv * swt[k * 40 + j0 + j];
    }
    #pragma unroll
    for (int j = 0; j < 10; j++) out[(size_t)gn * 40 + j0 + j] = acc[j];
}

// ================= launch ======================================================
extern "C" void kernel_launch(void* const* d_in, const int* in_sizes, int n_in,
                              void* d_out, int out_size) {
    const float* x   = (const float*)d_in[0];
    const int*   ei  = (const int*)d_in[1];
    const float* W0  = (const float*)d_in[2];
    const float* as0 = (const float*)d_in[3];
    const float* ad0 = (const float*)d_in[4];
    const float* b0  = (const float*)d_in[5];
    const float* W1  = (const float*)d_in[6];
    const float* as1 = (const float*)d_in[7];
    const float* ad1 = (const float*)d_in[8];
    const float* b1  = (const float*)d_in[9];
    const float* W2  = (const float*)d_in[10];
    const float* as2 = (const float*)d_in[11];
    const float* ad2 = (const float*)d_in[12];
    const float* b2  = (const float*)d_in[13];
    const float* lw  = (const float*)d_in[14];
    const float* lb  = (const float*)d_in[15];
    float* out = (float*)d_out;

    float *p_h, *p_feat;
    cudaGetSymbolAddress((void**)&p_h,    g_h);
    cudaGetSymbolAddress((void**)&p_feat, g_feat);

    const int T = 256;
    const int WPB = T / 32;          // warps per block
    const int NPB16 = T / 16;        // half-warp segments per block

    // ---- CSR build (once) ----
    detect_dtype<<<1, 32>>>(ei);
    clear_deg<<<cdiv(NN, T), T>>>();
    build_edges<<<cdiv(ETOT, T), T>>>(ei);
    scan_a<<<NB, 256>>>();
    scan_b<<<1, 32>>>();
    scan_c<<<NB, 256>>>();
    scatter_csr<<<cdiv(ETOT, T), T>>>();

    // ---- layer 0: 128 -> 4x32, concat ----
    gemm_big<<<cdiv(NN, 128), 256>>>(x, W0, p_h, as0, ad0);
    csr_softmax<4><<<cdiv(NN, NPB16), T>>>();
    csr_aggregate<4><<<cdiv(NN, WPB), T>>>(p_h, b0);

    // ---- layer 1: 128 -> 4x32, concat ----
    gemm_big<<<cdiv(NN, 128), 256>>>(p_feat, W1, p_h, as1, ad1);
    csr_softmax<4><<<cdiv(NN, NPB16), T>>>();
    csr_aggregate<4><<<cdiv(NN, WPB), T>>>(p_h, b1);

    // ---- layer 2: 128 -> 32, heads=1, mean(=identity) ----
    gemm_small<<<cdiv(NN, 64), 256>>>(p_feat, W2, p_h, as2, ad2);
    csr_softmax<1><<<cdiv(NN, NPB16), T>>>();
    csr_aggregate<1><<<cdiv(NN, WPB), T>>>(p_h, b2);

    // ---- final linear 32 -> 40 ----
    final_linear<<<cdiv(NN, 64), T>>>(p_feat, lw, lb, out);
}

// round 8
// speedup vs baseline: 1.8345x; 1.0296x over previous
#include <cuda_runtime.h>

#define NN 100000
#define EE 1600000
#define ETOT (EE + NN)      // edges + self loops
#define FH 128              // heads*channels for layers 0/1
#define CC 32               // channels per head
#define NCLS 40
#define FULL 0xffffffffu

// ---------------- scratch (device globals; no allocation allowed) ------------
__device__ __align__(16) float g_h[NN * FH];      // transformed features (x @ W)
__device__ __align__(16) float g_feat[NN * FH];   // layer output features
__device__ __align__(16) float g_as[NN * 4];
__device__ __align__(16) float g_ad[NN * 4];
__device__ int   g_csrc[ETOT];        // CSR: src per edge, grouped by dst
__device__ int   g_deg[NN];
__device__ int   g_rowptr[NN + 1];
__device__ int   g_cursor[NN];
__device__ int   g_bsum[128];
__device__ int   g_boff[128];
__device__ int   g_is64;

#define SCAN_CHUNK 1024
#define NB ((NN + SCAN_CHUNK - 1) / SCAN_CHUNK)   // 98

static inline int cdiv(int a, int b) { return (a + b - 1) / b; }

// ================= edge ingestion + CSR build =================================
__global__ void detect_dtype(const int* __restrict__ e) {
    if (blockIdx.x != 0 || threadIdx.x != 0) return;
    int any = 0;
    for (int i = 0; i < 4096; i++) any |= e[2 * i + 1];
    g_is64 = (any == 0) ? 1 : 0;
}

// init deg to 1: the self-loop is pre-counted
__global__ void init_deg() {
    int i = blockIdx.x * blockDim.x + threadIdx.x;
    if (i < NN) g_deg[i] = 1;
}

__global__ void deg_count(const int* __restrict__ e) {
    int i = blockIdx.x * blockDim.x + threadIdx.x;
    if (i >= EE) return;
    int d = g_is64 ? e[2 * ((size_t)EE + i)] : e[EE + i];
    atomicAdd(&g_deg[d], 1);
}

__global__ void scan_a() {
    __shared__ int sm[256];
    int blk = blockIdx.x, tid = threadIdx.x;
    int base = blk * SCAN_CHUNK + tid * 4;
    int t = 0;
    #pragma unroll
    for (int i = 0; i < 4; i++) if (base + i < NN) t += g_deg[base + i];
    sm[tid] = t;
    __syncthreads();
    for (int o = 128; o > 0; o >>= 1) {
        if (tid < o) sm[tid] += sm[tid + o];
        __syncthreads();
    }
    if (tid == 0) g_bsum[blk] = sm[0];
}

__global__ void scan_b() {
    if (threadIdx.x != 0) return;
    int run = 0;
    for (int i = 0; i < NB; i++) { g_boff[i] = run; run += g_bsum[i]; }
}

__global__ void scan_c() {
    int blk = blockIdx.x, tid = threadIdx.x;
    int base = blk * SCAN_CHUNK + tid * 4;
    int v[4];
    #pragma unroll
    for (int i = 0; i < 4; i++) v[i] = (base + i < NN) ? g_deg[base + i] : 0;
    int tsum = v[0] + v[1] + v[2] + v[3];
    int lane = tid & 31, wid = tid >> 5;
    int inc = tsum;
    #pragma unroll
    for (int o = 1; o < 32; o <<= 1) {
        int t = __shfl_up_sync(FULL, inc, o);
        if (lane >= o) inc += t;
    }
    __shared__ int wsum[8];
    if (lane == 31) wsum[wid] = inc;
    __syncthreads();
    if (tid < 8) {
        int t = wsum[tid];
        #pragma unroll
        for (int o = 1; o < 8; o <<= 1) {
            int u = __shfl_up_sync(0xff, t, o);
            if (tid >= o) t += u;
        }
        wsum[tid] = t;
    }
    __syncthreads();
    int excl = inc - tsum + (wid > 0 ? wsum[wid - 1] : 0) + g_boff[blk];
    #pragma unroll
    for (int i = 0; i < 4; i++) {
        if (base + i < NN) { g_rowptr[base + i] = excl; g_cursor[base + i] = excl; }
        excl += v[i];
    }
    if (blk == 0 && tid == 0) g_rowptr[NN] = ETOT;
}

__global__ void scatter_csr(const int* __restrict__ e) {
    int i = blockIdx.x * blockDim.x + threadIdx.x;
    if (i >= ETOT) return;
    int s, d;
    if (i < EE) {
        if (g_is64) { s = e[2 * (size_t)i]; d = e[2 * ((size_t)EE + i)]; }
        else        { s = e[i];             d = e[EE + i]; }
    } else {
        s = i - EE; d = i - EE;
    }
    int pos = atomicAdd(&g_cursor[d], 1);
    g_csrc[pos] = s;
}

// ================= GEMM (big) + fused alpha =====================================
__global__ void gemm_big(const float* __restrict__ X, const float* __restrict__ W,
                         float* __restrict__ Y,
                         const float* __restrict__ as_, const float* __restrict__ ad_) {
    __shared__ __align__(16) float sxT[32 * 132];   // [k][row]
    __shared__ __align__(16) float sw[32 * 132];    // [k][col]
    const int tid = threadIdx.x;
    const int r0 = blockIdx.x * 128;
    const int rg = (tid >> 4) * 8;     // 16 row groups
    const int cg = (tid & 15) * 8;     // 16 col groups

    float acc[8][8];
    #pragma unroll
    for (int i = 0; i < 8; i++)
        #pragma unroll
        for (int j = 0; j < 8; j++) acc[i][j] = 0.0f;

    for (int kk = 0; kk < 128; kk += 32) {
        #pragma unroll
        for (int it = 0; it < 4; it++) {
            int idx = tid + it * 256;
            int row = idx >> 3;
            int kq  = idx & 7;
            int grow = r0 + row; if (grow >= NN) grow = NN - 1;
            float4 v = *(const float4*)&X[(size_t)grow * 128 + kk + kq * 4];
            sxT[(kq * 4 + 0) * 132 + row] = v.x;
            sxT[(kq * 4 + 1) * 132 + row] = v.y;
            sxT[(kq * 4 + 2) * 132 + row] = v.z;
            sxT[(kq * 4 + 3) * 132 + row] = v.w;
        }
        #pragma unroll
        for (int it = 0; it < 4; it++) {
            int idx = tid + it * 256;
            int k  = idx >> 5;
            int cq = idx & 31;
            *(float4*)&sw[k * 132 + cq * 4] =
                *(const float4*)&W[(size_t)(kk + k) * 128 + cq * 4];
        }
        __syncthreads();

        #pragma unroll
        for (int k = 0; k < 32; k++) {
            float4 a0 = *(const float4*)&sxT[k * 132 + rg];
            float4 a1 = *(const float4*)&sxT[k * 132 + rg + 4];
            float4 b0 = *(const float4*)&sw[k * 132 + cg];
            float4 b1 = *(const float4*)&sw[k * 132 + cg + 4];
            float ar[8] = {a0.x, a0.y, a0.z, a0.w, a1.x, a1.y, a1.z, a1.w};
            float bc[8] = {b0.x, b0.y, b0.z, b0.w, b1.x, b1.y, b1.z, b1.w};
            #pragma unroll
            for (int i = 0; i < 8; i++)
                #pragma unroll
                for (int j = 0; j < 8; j++)
                    acc[i][j] += ar[i] * bc[j];
        }
        __syncthreads();
    }

    #pragma unroll
    for (int i = 0; i < 8; i++) {
        int row = r0 + rg + i;
        if (row < NN) {
            float4 o0 = {acc[i][0], acc[i][1], acc[i][2], acc[i][3]};
            float4 o1 = {acc[i][4], acc[i][5], acc[i][6], acc[i][7]};
            *(float4*)&Y[(size_t)row * 128 + cg]     = o0;
            *(float4*)&Y[(size_t)row * 128 + cg + 4] = o1;
        }
    }

    // fused alpha: cols [cg, cg+8) lie inside head = cg>>5.
    float av[8], dv[8];
    #pragma unroll
    for (int j = 0; j < 8; j++) { av[j] = as_[cg + j]; dv[j] = ad_[cg + j]; }
    float ps[8], pd[8];
    #pragma unroll
    for (int i = 0; i < 8; i++) {
        float s = 0.0f, d = 0.0f;
        #pragma unroll
        for (int j = 0; j < 8; j++) { s += acc[i][j] * av[j]; d += acc[i][j] * dv[j]; }
        ps[i] = s; pd[i] = d;
    }
    #pragma unroll
    for (int i = 0; i < 8; i++) {
        ps[i] += __shfl_xor_sync(FULL, ps[i], 1);
        pd[i] += __shfl_xor_sync(FULL, pd[i], 1);
        ps[i] += __shfl_xor_sync(FULL, ps[i], 2);
        pd[i] += __shfl_xor_sync(FULL, pd[i], 2);
    }
    if ((tid & 3) == 0) {
        int head = (tid & 15) >> 2;
        #pragma unroll
        for (int i = 0; i < 8; i++) {
            int row = r0 + rg + i;
            if (row < NN) {
                g_as[row * 4 + head] = ps[i];
                g_ad[row * 4 + head] = pd[i];
            }
        }
    }
}

// ================= GEMM (small) + fused alpha: Y[N,32] = X @ W[128,32] =========
__global__ void gemm_small(const float* __restrict__ X, const float* __restrict__ W,
                           float* __restrict__ Y,
                           const float* __restrict__ as_, const float* __restrict__ ad_) {
    constexpr int SXP = 68;
    constexpr int SWP = 36;
    __shared__ __align__(16) float sxT[64 * SXP];
    __shared__ __align__(16) float sw[64 * SWP];
    const int tid = threadIdx.x;
    const int r0 = blockIdx.x * 64;

    const int rg = (tid >> 4) * 4;
    const int cg = (tid & 15) * 2;
    float acc[4][2];
    #pragma unroll
    for (int i = 0; i < 4; i++) { acc[i][0] = 0.0f; acc[i][1] = 0.0f; }

    for (int kk = 0; kk < 128; kk += 64) {
        for (int idx = tid; idx < 64 * 64; idx += 256) {
            int k = idx & 63;
            int r = idx >> 6;
            int row = r0 + r; if (row >= NN) row = NN - 1;
            sxT[k * SXP + r] = X[(size_t)row * 128 + kk + k];
        }
        for (int idx = tid; idx < 64 * 8; idx += 256) {
            int k = idx / 8;
            int jq = (idx % 8) * 4;
            *(float4*)&sw[k * SWP + jq] =
                *(const float4*)&W[(size_t)(kk + k) * 32 + jq];
        }
        __syncthreads();

        #pragma unroll 8
        for (int k = 0; k < 64; k++) {
            float4 a = *(const float4*)&sxT[k * SXP + rg];
            float2 b = *(const float2*)&sw[k * SWP + cg];
            acc[0][0] += a.x * b.x; acc[0][1] += a.x * b.y;
            acc[1][0] += a.y * b.x; acc[1][1] += a.y * b.y;
            acc[2][0] += a.z * b.x; acc[2][1] += a.z * b.y;
            acc[3][0] += a.w * b.x; acc[3][1] += a.w * b.y;
        }
        __syncthreads();
    }

    #pragma unroll
    for (int i = 0; i < 4; i++) {
        int row = r0 + rg + i;
        if (row < NN) {
            float2 o = {acc[i][0], acc[i][1]};
            *(float2*)&Y[(size_t)row * 32 + cg] = o;
        }
    }

    float a0 = as_[cg], a1 = as_[cg + 1];
    float d0 = ad_[cg], d1 = ad_[cg + 1];
    float ps[4], pd[4];
    #pragma unroll
    for (int i = 0; i < 4; i++) {
        ps[i] = acc[i][0] * a0 + acc[i][1] * a1;
        pd[i] = acc[i][0] * d0 + acc[i][1] * d1;
    }
    #pragma unroll
    for (int o = 1; o < 16; o <<= 1) {
        #pragma unroll
        for (int i = 0; i < 4; i++) {
            ps[i] += __shfl_xor_sync(FULL, ps[i], o);
            pd[i] += __shfl_xor_sync(FULL, pd[i], o);
        }
    }
    if ((tid & 15) == 0) {
        #pragma unroll
        for (int i = 0; i < 4; i++) {
            int row = r0 + rg + i;
            if (row < NN) { g_as[row] = ps[i]; g_ad[row] = pd[i]; }
        }
    }
}

// ====== merged segment-softmax + pull aggregation: ONE warp per node ===========
// pass 1: per-head max over in-edges (float4 gather of g_as).
// pass 2: recompute w = exp(leaky(as+ad)-m) per edge, accumulate sum(w*row) and
//         den simultaneously; normalize + bias + relu at the end. No g_e array.
__device__ __forceinline__ float leaky(float x) { return x > 0.0f ? x : 0.2f * x; }

template<int HH>
__global__ void csr_softagg(const float* __restrict__ hf,
                            const float* __restrict__ bias) {
    int n = (blockIdx.x * blockDim.x + threadIdx.x) >> 5;
    int lane = threadIdx.x & 31;
    if (n >= NN) return;
    int off = g_rowptr[n];
    int end = g_rowptr[n + 1];

    if constexpr (HH == 4) {
        const int head = lane >> 3;
        // ---- pass 1: per-head max ----
        float mx = -1e30f, my = -1e30f, mz = -1e30f, mw = -1e30f;
        for (int p = off + lane; p < end; p += 32) {
            int s = __ldg(&g_csrc[p]);
            float4 a = *(const float4*)&g_as[s * 4];
            mx = fmaxf(mx, a.x); my = fmaxf(my, a.y);
            mz = fmaxf(mz, a.z); mw = fmaxf(mw, a.w);
        }
        #pragma unroll
        for (int o = 16; o >= 1; o >>= 1) {
            mx = fmaxf(mx, __shfl_xor_sync(FULL, mx, o));
            my = fmaxf(my, __shfl_xor_sync(FULL, my, o));
            mz = fmaxf(mz, __shfl_xor_sync(FULL, mz, o));
            mw = fmaxf(mw, __shfl_xor_sync(FULL, mw, o));
        }
        float4 adv = *(const float4*)&g_ad[n * 4];
        // leaky monotone + ad const per node: max leaky(as+ad) = leaky(max as + ad)
        mx = leaky(mx + adv.x); my = leaky(my + adv.y);
        mz = leaky(mz + adv.z); mw = leaky(mw + adv.w);
        float mh   = head == 0 ? mx : head == 1 ? my : head == 2 ? mz : mw;
        float adh  = head == 0 ? adv.x : head == 1 ? adv.y : head == 2 ? adv.z : adv.w;

        // ---- pass 2: weighted row accumulation + den ----
        float4 acc = {0.0f, 0.0f, 0.0f, 0.0f};
        float den = 0.0f;
        #pragma unroll 2
        for (int p = off; p < end; p++) {
            int s = __ldg(&g_csrc[p]);                       // warp-uniform
            float a = __ldg(&g_as[s * 4 + head]);            // 1 sector / warp
            float w = __expf(leaky(a + adh) - mh);
            den += w;                                        // identical within head
            const float4 v = *(const float4*)&hf[(size_t)s * 128 + lane * 4];
            acc.x += w * v.x; acc.y += w * v.y;
            acc.z += w * v.z; acc.w += w * v.w;
        }
        float inv = 1.0f / (den + 1e-16f);
        float4 bv = *(const float4*)&bias[lane * 4];
        float4 o;
        o.x = fmaxf(acc.x * inv + bv.x, 0.0f);
        o.y = fmaxf(acc.y * inv + bv.y, 0.0f);
        o.z = fmaxf(acc.z * inv + bv.z, 0.0f);
        o.w = fmaxf(acc.w * inv + bv.w, 0.0f);
        *(float4*)&g_feat[(size_t)n * 128 + lane * 4] = o;
    } else {
        // ---- pass 1: max ----
        float m = -1e30f;
        for (int p = off + lane; p < end; p += 32)
            m = fmaxf(m, __ldg(&g_as[g_csrc[p]]));
        #pragma unroll
        for (int o = 16; o >= 1; o >>= 1) m = fmaxf(m, __shfl_xor_sync(FULL, m, o));
        float adh = g_ad[n];
        m = leaky(m + adh);
        // ---- pass 2 ----
        float acc = 0.0f, den = 0.0f;
        #pragma unroll 2
        for (int p = off; p < end; p++) {
            int s = __ldg(&g_csrc[p]);
            float w = __expf(leaky(__ldg(&g_as[s]) + adh) - m);
            den += w;
            acc += w * hf[(size_t)s * 32 + lane];
        }
        float inv = 1.0f / (den + 1e-16f);
        float v = acc * inv + bias[lane];
        g_feat[(size_t)n * 32 + lane] = v > 0.0f ? v : 0.0f;
    }
}

// ================= final linear 32 -> 40 =======================================
__global__ void final_linear(const float* __restrict__ xin,
                             const float* __restrict__ w,
                             const float* __restrict__ b,
                             float* __restrict__ out) {
    __shared__ float swt[32 * 40];
    __shared__ float sxr[64 * 33];
    int tid = threadIdx.x;
    int n0 = blockIdx.x * 64;
    for (int i = tid; i < 32 * 40; i += 256) swt[i] = w[i];
    for (int i = tid; i < 64 * 32; i += 256) {
        int n = i >> 5, c = i & 31;
        int gn = n0 + n;
        sxr[n * 33 + c] = (gn < NN) ? xin[(size_t)gn * 32 + c] : 0.0f;
    }
    __syncthreads();
    int nl = tid >> 2;
    int j0 = (tid & 3) * 10;
    int gn = n0 + nl;
    if (gn >= NN) return;
    float acc[10];
    #pragma unroll
    for (int j = 0; j < 10; j++) acc[j] = b[j0 + j];
    #pragma unroll
    for (int k = 0; k < 32; k++) {
        float xv = sxr[nl * 33 + k];
        #pragma unroll
        for (int j = 0; j < 10; j++) acc[j] += xv * swt[k * 40 + j0 + j];
    }
    #pragma unroll
    for (int j = 0; j < 10; j++) out[(size_t)gn * 40 + j0 + j] = acc[j];
}

// ================= launch ======================================================
extern "C" void kernel_launch(void* const* d_in, const int* in_sizes, int n_in,
                              void* d_out, int out_size) {
    const float* x   = (const float*)d_in[0];
    const int*   ei  = (const int*)d_in[1];
    const float* W0  = (const float*)d_in[2];
    const float* as0 = (const float*)d_in[3];
    const float* ad0 = (const float*)d_in[4];
    const float* b0  = (const float*)d_in[5];
    const float* W1  = (const float*)d_in[6];
    const float* as1 = (const float*)d_in[7];
    const float* ad1 = (const float*)d_in[8];
    const float* b1  = (const float*)d_in[9];
    const float* W2  = (const float*)d_in[10];
    const float* as2 = (const float*)d_in[11];
    const float* ad2 = (const float*)d_in[12];
    const float* b2  = (const float*)d_in[13];
    const float* lw  = (const float*)d_in[14];
    const float* lb  = (const float*)d_in[15];
    float* out = (float*)d_out;

    float *p_h, *p_feat;
    cudaGetSymbolAddress((void**)&p_h,    g_h);
    cudaGetSymbolAddress((void**)&p_feat, g_feat);

    const int T = 256;
    const int WPB = T / 32;          // warps per block

    // ---- CSR build (once) ----
    detect_dtype<<<1, 32>>>(ei);
    init_deg<<<cdiv(NN, T), T>>>();
    deg_count<<<cdiv(EE, T), T>>>(ei);
    scan_a<<<NB, 256>>>();
    scan_b<<<1, 32>>>();
    scan_c<<<NB, 256>>>();
    scatter_csr<<<cdiv(ETOT, T), T>>>(ei);

    // ---- layer 0: 128 -> 4x32, concat ----
    gemm_big<<<cdiv(NN, 128), 256>>>(x, W0, p_h, as0, ad0);
    csr_softagg<4><<<cdiv(NN, WPB), T>>>(p_h, b0);

    // ---- layer 1: 128 -> 4x32, concat ----
    gemm_big<<<cdiv(NN, 128), 256>>>(p_feat, W1, p_h, as1, ad1);
    csr_softagg<4><<<cdiv(NN, WPB), T>>>(p_h, b1);

    // ---- layer 2: 128 -> 32, heads=1, mean(=identity) ----
    gemm_small<<<cdiv(NN, 64), 256>>>(p_feat, W2, p_h, as2, ad2);
    csr_softagg<1><<<cdiv(NN, WPB), T>>>(p_h, b2);

    // ---- final linear 32 -> 40 ----
    final_linear<<<cdiv(NN, 64), T>>>(p_feat, lw, lb, out);
}